// round 10
// baseline (speedup 1.0000x reference)
#include <cuda_runtime.h>
#include <cuda_fp16.h>
#include <cstdint>

#define SEQ   2048
#define DIM   4096
#define NH    32
#define NKV   8
#define HD    128
#define KVDIM 1024   // NKV*HD

// ---------------- scratch (static device globals; no allocations) ----------
__device__ float  g_q[SEQ * DIM];        // q proj fp32
__device__ float  g_k[SEQ * KVDIM];      // k proj fp32
__device__ __half g_xh[SEQ * DIM];       // x fp16
__device__ __half g_qh[SEQ * DIM];       // roped+scaled q fp16
__device__ __half g_kh[SEQ * KVDIM];     // roped k fp16
__device__ __half g_vh[SEQ * KVDIM];     // v fp16 (direct GEMM output)
__device__ __half g_ah[SEQ * DIM];       // attention out fp16
__device__ __half g_wqh[DIM * DIM];      // wq^T [N][K] fp16
__device__ __half g_wkh[KVDIM * DIM];
__device__ __half g_wvh[KVDIM * DIM];
__device__ __half g_woh[DIM * DIM];

// ---------------- PTX helpers ----------------------------------------------
__device__ __forceinline__ uint32_t smem_u32(const void* p) {
    uint32_t a;
    asm("{ .reg .u64 t; cvta.to.shared.u64 t, %1; cvt.u32.u64 %0, t; }"
        : "=r"(a) : "l"(p));
    return a;
}
__device__ __forceinline__ void cpasync16(uint32_t dst, const void* src) {
    asm volatile("cp.async.cg.shared.global [%0], [%1], 16;" :: "r"(dst), "l"(src));
}
#define CP_COMMIT() asm volatile("cp.async.commit_group;" ::: "memory")
#define CP_WAIT(N)  asm volatile("cp.async.wait_group %0;" :: "n"(N) : "memory")

__device__ __forceinline__ void ldsm4(uint32_t* r, uint32_t a) {
    asm volatile("ldmatrix.sync.aligned.m8n8.x4.shared.b16 {%0,%1,%2,%3}, [%4];"
        : "=r"(r[0]), "=r"(r[1]), "=r"(r[2]), "=r"(r[3]) : "r"(a));
}
__device__ __forceinline__ void ldsm4t(uint32_t* r, uint32_t a) {
    asm volatile("ldmatrix.sync.aligned.m8n8.x4.trans.shared.b16 {%0,%1,%2,%3}, [%4];"
        : "=r"(r[0]), "=r"(r[1]), "=r"(r[2]), "=r"(r[3]) : "r"(a));
}
// D += A(16x16) * B(16x8), fp16 in, fp32 accum
__device__ __forceinline__ void mma16(float* c, const uint32_t* a,
                                      uint32_t b0, uint32_t b1) {
    asm volatile(
        "mma.sync.aligned.m16n8k16.row.col.f32.f16.f16.f32 "
        "{%0,%1,%2,%3}, {%4,%5,%6,%7}, {%8,%9}, {%0,%1,%2,%3};"
        : "+f"(c[0]), "+f"(c[1]), "+f"(c[2]), "+f"(c[3])
        : "r"(a[0]), "r"(a[1]), "r"(a[2]), "r"(a[3]), "r"(b0), "r"(b1));
}
__device__ __forceinline__ uint32_t f2h2(float lo, float hi) {
    uint32_t d;
    asm("cvt.rn.f16x2.f32 %0, %1, %2;" : "=r"(d) : "f"(hi), "f"(lo));
    return d;
}

// ---------------- fp16 GEMM: C[M,N] = A[M,K] @ BT[N,K]^T --------------------
// 128x256x32 CTA tile, 256 threads (8 warps 2x4, warp tile 64x64), 4-stage
// cp.async pipeline. smem rows padded to 80B (conflict-free ldmatrix, proven
// in round 9). Output type templated (fp32 or fp16).
#define G_ASZ   10240             // A: 128 rows * 80 B
#define G_STAGE 30720             // A 10240 + B 256*80
#define G_SMEM  (4 * G_STAGE)     // 122880 B

__device__ __forceinline__ void g_fill(uint32_t sbase, int slot,
                                       const __half* __restrict__ Ab,
                                       const __half* __restrict__ Bb,
                                       int K, int kt, int tid)
{
    const uint32_t sA = sbase + slot * G_STAGE;
    const uint32_t sB = sA + G_ASZ;
    const __half* ag = Ab + (size_t)kt * 32;
    const __half* bg = Bb + (size_t)kt * 32;
    #pragma unroll
    for (int j = 0; j < 2; j++) {             // A: 128 rows x 4 chunks
        int idx = tid + j * 256;
        int r = idx >> 2, c = idx & 3;
        cpasync16(sA + r * 80 + c * 16, ag + (size_t)r * K + c * 8);
    }
    #pragma unroll
    for (int j = 0; j < 4; j++) {             // B: 256 rows x 4 chunks
        int idx = tid + j * 256;
        int r = idx >> 2, c = idx & 3;
        cpasync16(sB + r * 80 + c * 16, bg + (size_t)r * K + c * 8);
    }
    CP_COMMIT();
}

template <typename OutT>
__global__ __launch_bounds__(256, 1)
void gemm_h(const __half* __restrict__ A, const __half* __restrict__ BT,
            OutT* __restrict__ C, int N, int K)
{
    extern __shared__ char smem[];
    const uint32_t sbase = smem_u32(smem);
    const int tid = threadIdx.x, lane = tid & 31, wid = tid >> 5;
    const int g = lane >> 2, tg = lane & 3;
    const int wm = (wid & 1) * 64, wn = (wid >> 1) * 64;
    const int rowBase = blockIdx.y * 128, colBase = blockIdx.x * 256;

    const __half* Ab = A  + (size_t)rowBase * K;
    const __half* Bb = BT + (size_t)colBase * K;
    const int T = K / 32;

    // per-lane ldmatrix base offsets
    const uint32_t aoff = (uint32_t)((wm + (lane & 15)) * 80 + (lane >> 4) * 16);
    const uint32_t boff = (uint32_t)((wn + (lane & 7) + ((lane >> 4) << 3)) * 80
                                     + ((lane >> 3) & 1) * 16);

    float acc[4][8][4];
    #pragma unroll
    for (int mi = 0; mi < 4; mi++)
        #pragma unroll
        for (int ni = 0; ni < 8; ni++)
            #pragma unroll
            for (int c = 0; c < 4; c++) acc[mi][ni][c] = 0.f;

    #pragma unroll
    for (int s = 0; s < 3; s++) g_fill(sbase, s, Ab, Bb, K, s, tid);

    for (int t = 0; t < T; t++) {
        CP_WAIT(2);
        __syncthreads();
        const uint32_t sA = sbase + (t & 3) * G_STAGE;
        const uint32_t sB = sA + G_ASZ;
        #pragma unroll
        for (int ks = 0; ks < 2; ks++) {
            uint32_t a[4][4];
            #pragma unroll
            for (int mi = 0; mi < 4; mi++)
                ldsm4(a[mi], sA + aoff + mi * 1280 + ks * 32);
            #pragma unroll
            for (int nbp = 0; nbp < 4; nbp++) {
                uint32_t b[4];
                ldsm4(b, sB + boff + nbp * 1280 + ks * 32);
                #pragma unroll
                for (int mi = 0; mi < 4; mi++) {
                    mma16(acc[mi][nbp * 2],     a[mi], b[0], b[1]);
                    mma16(acc[mi][nbp * 2 + 1], a[mi], b[2], b[3]);
                }
            }
        }
        if (t + 3 < T) g_fill(sbase, (t + 3) & 3, Ab, Bb, K, t + 3, tid);
        else           CP_COMMIT();   // keep wait_group accounting uniform
    }

    #pragma unroll
    for (int mi = 0; mi < 4; mi++) {
        #pragma unroll
        for (int ni = 0; ni < 8; ni++) {
            int r0 = rowBase + wm + mi * 16 + g;
            int cc = colBase + wn + ni * 8 + tg * 2;
            if (sizeof(OutT) == 4) {
                float2 t0; t0.x = acc[mi][ni][0]; t0.y = acc[mi][ni][1];
                float2 t1; t1.x = acc[mi][ni][2]; t1.y = acc[mi][ni][3];
                *(float2*)&((float*)C)[(size_t)r0 * N + cc]       = t0;
                *(float2*)&((float*)C)[(size_t)(r0 + 8) * N + cc] = t1;
            } else {
                *(uint32_t*)&((__half*)C)[(size_t)r0 * N + cc] =
                    f2h2(acc[mi][ni][0], acc[mi][ni][1]);
                *(uint32_t*)&((__half*)C)[(size_t)(r0 + 8) * N + cc] =
                    f2h2(acc[mi][ni][2], acc[mi][ni][3]);
            }
        }
    }
}

// ---------------- pre-passes -------------------------------------------------
__global__ void conv_half4(const float* __restrict__ in, __half* __restrict__ out,
                           int n4)
{
    int i = blockIdx.x * blockDim.x + threadIdx.x;
    if (i >= n4) return;
    float4 v = ((const float4*)in)[i];
    uint2 o;
    o.x = f2h2(v.x, v.y);
    o.y = f2h2(v.z, v.w);
    ((uint2*)out)[i] = o;
}

// W[K][N] fp32 row-major -> WT[N][K] fp16 row-major
__global__ void transpose_h(const float* __restrict__ W, __half* __restrict__ WT,
                            int K, int N)
{
    __shared__ float t[32][33];
    int x = blockIdx.x * 32 + threadIdx.x;
    int y0 = blockIdx.y * 32;
    #pragma unroll
    for (int j = threadIdx.y; j < 32; j += 8)
        t[j][threadIdx.x] = W[(size_t)(y0 + j) * N + x];
    __syncthreads();
    int k = y0 + threadIdx.x;
    int n0 = blockIdx.x * 32;
    #pragma unroll
    for (int j = threadIdx.y; j < 32; j += 8)
        WT[(size_t)(n0 + j) * K + k] = __float2half_rn(t[threadIdx.x][j]);
}

// ---------------- RoPE + fp16 conversion ------------------------------------
__global__ void rope_h(const float* __restrict__ q, const float* __restrict__ k,
                       const float* __restrict__ f,
                       __half* __restrict__ qh, __half* __restrict__ kh)
{
    int idx = blockIdx.x * blockDim.x + threadIdx.x;
    const int total = SEQ * (NH + NKV) * (HD / 2);
    if (idx >= total) return;
    int i = idx & 63;
    int h = (idx >> 6) % (NH + NKV);
    int s = idx / ((NH + NKV) * 64);
    const float scale = 0.08838834764831845f;   // 1/sqrt(128)

    float c = f[s * 128 + 2 * i];
    float d = f[s * 128 + 2 * i + 1];
    if (h < NH) {
        size_t off = (size_t)s * DIM + h * HD + 2 * i;
        float a = q[off], b = q[off + 1];
        qh[off]     = __float2half_rn((a * c - b * d) * scale);
        qh[off + 1] = __float2half_rn((a * d + b * c) * scale);
    } else {
        size_t off = (size_t)s * KVDIM + (h - NH) * HD + 2 * i;
        float a = k[off], b = k[off + 1];
        kh[off]     = __float2half_rn(a * c - b * d);
        kh[off + 1] = __float2half_rn(a * d + b * c);
    }
}

// ---------------- causal flash attention (fp16 mma, GQA) --------------------
#define FKR   136                         // halves per K/V smem row
#define FTILE (64 * FKR * 2)              // 17408 B
#define F_SMEM (4 * FTILE)                // K0,V0,K1,V1

__device__ __forceinline__ void f_fill(uint32_t sbase, int buf, int kt,
                                       const __half* __restrict__ kb,
                                       const __half* __restrict__ vb, int tid)
{
    const uint32_t kd = sbase + buf * (2 * FTILE);
    const uint32_t vd = kd + FTILE;
    const __half* kg = kb + (size_t)(kt * 64) * KVDIM;
    const __half* vg = vb + (size_t)(kt * 64) * KVDIM;
    #pragma unroll
    for (int j = 0; j < 8; j++) {
        int idx = tid + j * 128;
        int r = idx >> 4, c = idx & 15;
        cpasync16(kd + r * 272 + c * 16, kg + (size_t)r * KVDIM + c * 8);
        cpasync16(vd + r * 272 + c * 16, vg + (size_t)r * KVDIM + c * 8);
    }
    CP_COMMIT();
}

__global__ __launch_bounds__(128, 2)
void flash_h(const __half* __restrict__ q, const __half* __restrict__ k,
             const __half* __restrict__ v, __half* __restrict__ o)
{
    extern __shared__ char smem[];
    const uint32_t sbase = smem_u32(smem);
    const int tid = threadIdx.x, lane = tid & 31, w = tid >> 5;
    const int g = lane >> 2, tg = lane & 3;
    const int h = blockIdx.y, qt = blockIdx.x;
    const int q0 = qt * 64, khd = h >> 2;

    const __half* kb = k + khd * HD;
    const __half* vb = v + khd * HD;

    // ---- stage Q tile into buf1-K region (unused at kt=0) + overlap fill0
    {
        const __half* qg = q + (size_t)q0 * DIM + h * HD;
        const uint32_t qdst = sbase + 2 * FTILE;   // buf1 K region
        #pragma unroll
        for (int j = 0; j < 8; j++) {
            int idx = tid + j * 128;
            int r = idx >> 4, c = idx & 15;
            cpasync16(qdst + r * 272 + c * 16, qg + (size_t)r * DIM + c * 8);
        }
        CP_COMMIT();
    }
    f_fill(sbase, 0, 0, kb, vb, tid);   // overlap K/V tile 0 with Q load
    CP_WAIT(1);                          // Q group done (fill0 may be pending)
    __syncthreads();

    uint32_t qa[8][4];
    {
        const uint32_t qoff = sbase + 2 * FTILE
            + (uint32_t)((w * 16 + (lane & 15)) * 272 + (lane >> 4) * 16);
        #pragma unroll
        for (int ks = 0; ks < 8; ks++) ldsm4(qa[ks], qoff + ks * 32);
    }
    __syncthreads();   // Q frags read before buf1 can be refilled

    float m0 = -1e30f, m1 = -1e30f, l0 = 0.f, l1 = 0.f;
    float oacc[16][4];
    #pragma unroll
    for (int nf = 0; nf < 16; nf++)
        #pragma unroll
        for (int c = 0; c < 4; c++) oacc[nf][c] = 0.f;

    const uint32_t kboff = (uint32_t)(((lane & 7) + ((lane >> 4) << 3)) * 272
                                      + ((lane >> 3) & 1) * 16);
    const uint32_t vboff = (uint32_t)(((lane & 7) + ((lane >> 3) & 1) * 8) * 272
                                      + (lane >> 4) * 16);

    for (int kt = 0; kt <= qt; kt++) {
        if (kt < qt) {
            f_fill(sbase, (kt + 1) & 1, kt + 1, kb, vb, tid);
            CP_WAIT(1);
        } else {
            CP_WAIT(0);
        }
        __syncthreads();
        const uint32_t kbase = sbase + (kt & 1) * (2 * FTILE);
        const uint32_t vbase = kbase + FTILE;

        // ---- S = Q @ K^T
        float s[8][4];
        #pragma unroll
        for (int nf = 0; nf < 8; nf++)
            #pragma unroll
            for (int c = 0; c < 4; c++) s[nf][c] = 0.f;
        #pragma unroll
        for (int ks = 0; ks < 8; ks++) {
            #pragma unroll
            for (int nbp = 0; nbp < 4; nbp++) {
                uint32_t b[4];
                ldsm4(b, kbase + kboff + nbp * 16 * 272 + ks * 32);
                mma16(s[nbp * 2],     qa[ks], b[0], b[1]);
                mma16(s[nbp * 2 + 1], qa[ks], b[2], b[3]);
            }
        }

        // ---- causal mask on diagonal tile
        if (kt == qt) {
            int r0 = w * 16 + g, r1 = r0 + 8;
            #pragma unroll
            for (int nf = 0; nf < 8; nf++) {
                int c = nf * 8 + tg * 2;
                if (c     > r0) s[nf][0] = -1e30f;
                if (c + 1 > r0) s[nf][1] = -1e30f;
                if (c     > r1) s[nf][2] = -1e30f;
                if (c + 1 > r1) s[nf][3] = -1e30f;
            }
        }

        // ---- online softmax; P packed to fp16 registers
        float mx0 = -1e30f, mx1 = -1e30f;
        #pragma unroll
        for (int nf = 0; nf < 8; nf++) {
            mx0 = fmaxf(mx0, fmaxf(s[nf][0], s[nf][1]));
            mx1 = fmaxf(mx1, fmaxf(s[nf][2], s[nf][3]));
        }
        mx0 = fmaxf(mx0, __shfl_xor_sync(0xffffffffu, mx0, 1));
        mx0 = fmaxf(mx0, __shfl_xor_sync(0xffffffffu, mx0, 2));
        mx1 = fmaxf(mx1, __shfl_xor_sync(0xffffffffu, mx1, 1));
        mx1 = fmaxf(mx1, __shfl_xor_sync(0xffffffffu, mx1, 2));

        float mn0 = fmaxf(m0, mx0), mn1 = fmaxf(m1, mx1);
        float al0 = __expf(m0 - mn0), al1 = __expf(m1 - mn1);
        float rs0 = 0.f, rs1 = 0.f;
        uint32_t ph[8][2];
        #pragma unroll
        for (int nf = 0; nf < 8; nf++) {
            float p0 = __expf(s[nf][0] - mn0);
            float p1 = __expf(s[nf][1] - mn0);
            float p2 = __expf(s[nf][2] - mn1);
            float p3 = __expf(s[nf][3] - mn1);
            rs0 += p0 + p1; rs1 += p2 + p3;
            ph[nf][0] = f2h2(p0, p1);   // row g
            ph[nf][1] = f2h2(p2, p3);   // row g+8
        }
        rs0 += __shfl_xor_sync(0xffffffffu, rs0, 1);
        rs0 += __shfl_xor_sync(0xffffffffu, rs0, 2);
        rs1 += __shfl_xor_sync(0xffffffffu, rs1, 1);
        rs1 += __shfl_xor_sync(0xffffffffu, rs1, 2);
        l0 = l0 * al0 + rs0;  l1 = l1 * al1 + rs1;
        m0 = mn0;  m1 = mn1;
        #pragma unroll
        for (int nf = 0; nf < 16; nf++) {
            oacc[nf][0] *= al0; oacc[nf][1] *= al0;
            oacc[nf][2] *= al1; oacc[nf][3] *= al1;
        }

        // ---- O += P @ V   (V via ldmatrix.trans)
        #pragma unroll
        for (int ksv = 0; ksv < 4; ksv++) {
            uint32_t a[4];
            a[0] = ph[2 * ksv][0];     a[1] = ph[2 * ksv][1];
            a[2] = ph[2 * ksv + 1][0]; a[3] = ph[2 * ksv + 1][1];
            #pragma unroll
            for (int nbp = 0; nbp < 8; nbp++) {
                uint32_t b[4];
                ldsm4t(b, vbase + vboff + ksv * 16 * 272 + nbp * 32);
                mma16(oacc[nbp * 2],     a, b[0], b[1]);
                mma16(oacc[nbp * 2 + 1], a, b[2], b[3]);
            }
        }
        __syncthreads();   // all warps done with this buffer before refill
    }

    // ---- epilogue: fp16 store (A operand of the wo GEMM)
    float inv0 = 1.f / l0, inv1 = 1.f / l1;
    __half* o0 = o + (size_t)(q0 + w * 16 + g) * DIM + h * HD;
    __half* o1 = o0 + (size_t)8 * DIM;
    #pragma unroll
    for (int nf = 0; nf < 16; nf++) {
        *(uint32_t*)&o0[nf * 8 + tg * 2] = f2h2(oacc[nf][0] * inv0, oacc[nf][1] * inv0);
        *(uint32_t*)&o1[nf * 8 + tg * 2] = f2h2(oacc[nf][2] * inv1, oacc[nf][3] * inv1);
    }
}

// ---------------- launch ------------------------------------------------------
extern "C" void kernel_launch(void* const* d_in, const int* in_sizes, int n_in,
                              void* d_out, int out_size)
{
    const float* x  = (const float*)d_in[0];
    // d_in[1] = cache_kv: unused (start_pos==0 => cache is pass-through)
    const float* fr = (const float*)d_in[2];
    const float* wq = (const float*)d_in[3];
    const float* wk = (const float*)d_in[4];
    const float* wv = (const float*)d_in[5];
    const float* wo = (const float*)d_in[6];
    float* out = (float*)d_out;

    float  *pq, *pk;
    __half *pxh, *pqh, *pkh, *pvh, *pah, *pwq, *pwk, *pwv, *pwo;
    cudaGetSymbolAddress((void**)&pq,  g_q);
    cudaGetSymbolAddress((void**)&pk,  g_k);
    cudaGetSymbolAddress((void**)&pxh, g_xh);
    cudaGetSymbolAddress((void**)&pqh, g_qh);
    cudaGetSymbolAddress((void**)&pkh, g_kh);
    cudaGetSymbolAddress((void**)&pvh, g_vh);
    cudaGetSymbolAddress((void**)&pah, g_ah);
    cudaGetSymbolAddress((void**)&pwq, g_wqh);
    cudaGetSymbolAddress((void**)&pwk, g_wkh);
    cudaGetSymbolAddress((void**)&pwv, g_wvh);
    cudaGetSymbolAddress((void**)&pwo, g_woh);

    cudaFuncSetAttribute(gemm_h<float>,
                         cudaFuncAttributeMaxDynamicSharedMemorySize, G_SMEM);
    cudaFuncSetAttribute(gemm_h<__half>,
                         cudaFuncAttributeMaxDynamicSharedMemorySize, G_SMEM);
    cudaFuncSetAttribute(flash_h,
                         cudaFuncAttributeMaxDynamicSharedMemorySize, F_SMEM);

    // --- pre-passes: fp16 conversion (+ weight transpose to [N][K]) ---
    conv_half4<<<(SEQ * DIM / 4 + 255) / 256, 256>>>(x, pxh, SEQ * DIM / 4);
    dim3 tb(32, 8);
    transpose_h<<<dim3(DIM / 32,   DIM / 32), tb>>>(wq, pwq, DIM, DIM);
    transpose_h<<<dim3(KVDIM / 32, DIM / 32), tb>>>(wk, pwk, DIM, KVDIM);
    transpose_h<<<dim3(KVDIM / 32, DIM / 32), tb>>>(wv, pwv, DIM, KVDIM);
    transpose_h<<<dim3(DIM / 32,   DIM / 32), tb>>>(wo, pwo, DIM, DIM);

    // --- QKV projections (fp16 mma, 128x256 tiles) ---
    gemm_h<float ><<<dim3(DIM / 256,   SEQ / 128), 256, G_SMEM>>>(pxh, pwq, pq,  DIM,   DIM);
    gemm_h<float ><<<dim3(KVDIM / 256, SEQ / 128), 256, G_SMEM>>>(pxh, pwk, pk,  KVDIM, DIM);
    gemm_h<__half><<<dim3(KVDIM / 256, SEQ / 128), 256, G_SMEM>>>(pxh, pwv, pvh, KVDIM, DIM);

    // --- RoPE + fp16 conversion ---
    const int rope_total = SEQ * (NH + NKV) * (HD / 2);
    rope_h<<<(rope_total + 255) / 256, 256>>>(pq, pk, fr, pqh, pkh);

    // --- causal GQA flash attention (fp16 mma) ---
    flash_h<<<dim3(SEQ / 64, NH), 128, F_SMEM>>>(pqh, pkh, pvh, pah);

    // --- output projection ---
    gemm_h<float><<<dim3(DIM / 256, SEQ / 128), 256, G_SMEM>>>(pah, pwo, out, DIM, DIM);
}

// round 11
// speedup vs baseline: 1.0988x; 1.0988x over previous
#include <cuda_runtime.h>
#include <cuda_fp16.h>
#include <cstdint>

#define SEQ   2048
#define DIM   4096
#define NH    32
#define NKV   8
#define HD    128
#define KVDIM 1024   // NKV*HD

// ---------------- scratch (static device globals; no allocations) ----------
__device__ __half g_xh[SEQ * DIM];       // x fp16
__device__ __half g_qh[SEQ * DIM];       // roped+scaled q fp16 (GEMM epilogue)
__device__ __half g_kh[SEQ * KVDIM];     // roped k fp16 (GEMM epilogue)
__device__ __half g_vh[SEQ * KVDIM];     // v fp16 (direct GEMM output)
__device__ __half g_ah[SEQ * DIM];       // attention out fp16
__device__ __half g_wqh[DIM * DIM];      // wq^T [N][K] fp16
__device__ __half g_wkh[KVDIM * DIM];
__device__ __half g_wvh[KVDIM * DIM];
__device__ __half g_woh[DIM * DIM];

// ---------------- PTX helpers ----------------------------------------------
__device__ __forceinline__ uint32_t smem_u32(const void* p) {
    uint32_t a;
    asm("{ .reg .u64 t; cvta.to.shared.u64 t, %1; cvt.u32.u64 %0, t; }"
        : "=r"(a) : "l"(p));
    return a;
}
__device__ __forceinline__ void cpasync16(uint32_t dst, const void* src) {
    asm volatile("cp.async.cg.shared.global [%0], [%1], 16;" :: "r"(dst), "l"(src));
}
#define CP_COMMIT() asm volatile("cp.async.commit_group;" ::: "memory")
#define CP_WAIT(N)  asm volatile("cp.async.wait_group %0;" :: "n"(N) : "memory")

__device__ __forceinline__ void ldsm4(uint32_t* r, uint32_t a) {
    asm volatile("ldmatrix.sync.aligned.m8n8.x4.shared.b16 {%0,%1,%2,%3}, [%4];"
        : "=r"(r[0]), "=r"(r[1]), "=r"(r[2]), "=r"(r[3]) : "r"(a));
}
__device__ __forceinline__ void ldsm4t(uint32_t* r, uint32_t a) {
    asm volatile("ldmatrix.sync.aligned.m8n8.x4.trans.shared.b16 {%0,%1,%2,%3}, [%4];"
        : "=r"(r[0]), "=r"(r[1]), "=r"(r[2]), "=r"(r[3]) : "r"(a));
}
// D += A(16x16) * B(16x8), fp16 in, fp32 accum
__device__ __forceinline__ void mma16(float* c, const uint32_t* a,
                                      uint32_t b0, uint32_t b1) {
    asm volatile(
        "mma.sync.aligned.m16n8k16.row.col.f32.f16.f16.f32 "
        "{%0,%1,%2,%3}, {%4,%5,%6,%7}, {%8,%9}, {%0,%1,%2,%3};"
        : "+f"(c[0]), "+f"(c[1]), "+f"(c[2]), "+f"(c[3])
        : "r"(a[0]), "r"(a[1]), "r"(a[2]), "r"(a[3]), "r"(b0), "r"(b1));
}
__device__ __forceinline__ uint32_t f2h2(float lo, float hi) {
    uint32_t d;
    asm("cvt.rn.f16x2.f32 %0, %1, %2;" : "=r"(d) : "f"(hi), "f"(lo));
    return d;
}

// ---------------- fp16 GEMM: C[M,N] = A[M,K] @ BT[N,K]^T --------------------
// 128x128x32 CTA tile, 256 threads (8 warps 2x4, warp tile 64x32), 4-stage
// cp.async pipeline, 2 CTAs/SM. RMODE: 0 = plain store, 1 = RoPE+scale (Q),
// 2 = RoPE (K). RoPE pairs (2i,2i+1) land on one thread's (c0,c1)/(c2,c3).
#define G_STAGE 20480             // A 128*80 + B 128*80
#define G_SMEM  (4 * G_STAGE)     // 81920 B -> 2 CTAs/SM

__device__ __forceinline__ void g_fill(uint32_t sbase, int slot,
                                       const __half* __restrict__ Ab,
                                       const __half* __restrict__ Bb,
                                       int K, int kt, int tid)
{
    const uint32_t sA = sbase + slot * G_STAGE;
    const uint32_t sB = sA + 10240;
    const __half* ag = Ab + (size_t)kt * 32;
    const __half* bg = Bb + (size_t)kt * 32;
    #pragma unroll
    for (int j = 0; j < 2; j++) {
        int idx = tid + j * 256;
        int r = idx >> 2, c = idx & 3;
        cpasync16(sA + r * 80 + c * 16, ag + (size_t)r * K + c * 8);
        cpasync16(sB + r * 80 + c * 16, bg + (size_t)r * K + c * 8);
    }
    CP_COMMIT();
}

template <typename OutT, int RMODE>
__global__ __launch_bounds__(256, 2)
void gemm_h(const __half* __restrict__ A, const __half* __restrict__ BT,
            OutT* __restrict__ C, const float* __restrict__ fr, int N, int K)
{
    extern __shared__ char smem[];
    const uint32_t sbase = smem_u32(smem);
    const int tid = threadIdx.x, lane = tid & 31, wid = tid >> 5;
    const int g = lane >> 2, tg = lane & 3;
    const int wm = (wid & 1) * 64, wn = (wid >> 1) * 32;
    const int rowBase = blockIdx.y * 128, colBase = blockIdx.x * 128;

    const __half* Ab = A  + (size_t)rowBase * K;
    const __half* Bb = BT + (size_t)colBase * K;
    const int T = K / 32;

    const uint32_t aoff = (uint32_t)((wm + (lane & 15)) * 80 + (lane >> 4) * 16);
    const uint32_t boff = (uint32_t)((wn + (lane & 7) + ((lane >> 4) << 3)) * 80
                                     + ((lane >> 3) & 1) * 16);

    float acc[4][4][4];
    #pragma unroll
    for (int mi = 0; mi < 4; mi++)
        #pragma unroll
        for (int ni = 0; ni < 4; ni++)
            #pragma unroll
            for (int c = 0; c < 4; c++) acc[mi][ni][c] = 0.f;

    #pragma unroll
    for (int s = 0; s < 3; s++) g_fill(sbase, s, Ab, Bb, K, s, tid);

    for (int t = 0; t < T; t++) {
        CP_WAIT(2);
        __syncthreads();
        const uint32_t sA = sbase + (t & 3) * G_STAGE;
        const uint32_t sB = sA + 10240;
        #pragma unroll
        for (int ks = 0; ks < 2; ks++) {
            uint32_t a[4][4], b[2][4];
            #pragma unroll
            for (int mi = 0; mi < 4; mi++)
                ldsm4(a[mi], sA + aoff + mi * 1280 + ks * 32);
            #pragma unroll
            for (int nbp = 0; nbp < 2; nbp++)
                ldsm4(b[nbp], sB + boff + nbp * 1280 + ks * 32);
            #pragma unroll
            for (int mi = 0; mi < 4; mi++) {
                mma16(acc[mi][0], a[mi], b[0][0], b[0][1]);
                mma16(acc[mi][1], a[mi], b[0][2], b[0][3]);
                mma16(acc[mi][2], a[mi], b[1][0], b[1][1]);
                mma16(acc[mi][3], a[mi], b[1][2], b[1][3]);
            }
        }
        if (t + 3 < T) g_fill(sbase, (t + 3) & 3, Ab, Bb, K, t + 3, tid);
        else           CP_COMMIT();   // keep wait_group accounting uniform
    }

    const float scale = 0.08838834764831845f;   // 1/sqrt(128)
    #pragma unroll
    for (int mi = 0; mi < 4; mi++) {
        #pragma unroll
        for (int ni = 0; ni < 4; ni++) {
            int r0 = rowBase + wm + mi * 16 + g;
            int r1 = r0 + 8;
            int cc = colBase + wn + ni * 8 + tg * 2;
            float v0 = acc[mi][ni][0], v1 = acc[mi][ni][1];
            float v2 = acc[mi][ni][2], v3 = acc[mi][ni][3];
            if (RMODE != 0) {
                // RoPE: (cc, cc+1) is a rotation pair within the head
                int fd = cc & (HD - 1);
                float2 f0 = *(const float2*)&fr[(size_t)r0 * HD + fd];
                float2 f1 = *(const float2*)&fr[(size_t)r1 * HD + fd];
                float t0 = v0 * f0.x - v1 * f0.y;
                float t1 = v0 * f0.y + v1 * f0.x;
                float t2 = v2 * f1.x - v3 * f1.y;
                float t3 = v2 * f1.y + v3 * f1.x;
                if (RMODE == 1) { t0 *= scale; t1 *= scale; t2 *= scale; t3 *= scale; }
                v0 = t0; v1 = t1; v2 = t2; v3 = t3;
            }
            if (sizeof(OutT) == 4) {
                float2 t0; t0.x = v0; t0.y = v1;
                float2 t1; t1.x = v2; t1.y = v3;
                *(float2*)&((float*)C)[(size_t)r0 * N + cc] = t0;
                *(float2*)&((float*)C)[(size_t)r1 * N + cc] = t1;
            } else {
                *(uint32_t*)&((__half*)C)[(size_t)r0 * N + cc] = f2h2(v0, v1);
                *(uint32_t*)&((__half*)C)[(size_t)r1 * N + cc] = f2h2(v2, v3);
            }
        }
    }
}

// ---------------- pre-passes -------------------------------------------------
__global__ void conv_half4(const float* __restrict__ in, __half* __restrict__ out,
                           int n4)
{
    int i = blockIdx.x * blockDim.x + threadIdx.x;
    if (i >= n4) return;
    float4 v = ((const float4*)in)[i];
    uint2 o;
    o.x = f2h2(v.x, v.y);
    o.y = f2h2(v.z, v.w);
    ((uint2*)out)[i] = o;
}

// W[K][N] fp32 row-major -> WT[N][K] fp16 row-major
__global__ void transpose_h(const float* __restrict__ W, __half* __restrict__ WT,
                            int K, int N)
{
    __shared__ float t[32][33];
    int x = blockIdx.x * 32 + threadIdx.x;
    int y0 = blockIdx.y * 32;
    #pragma unroll
    for (int j = threadIdx.y; j < 32; j += 8)
        t[j][threadIdx.x] = W[(size_t)(y0 + j) * N + x];
    __syncthreads();
    int k = y0 + threadIdx.x;
    int n0 = blockIdx.x * 32;
    #pragma unroll
    for (int j = threadIdx.y; j < 32; j += 8)
        WT[(size_t)(n0 + j) * K + k] = __float2half_rn(t[threadIdx.x][j]);
}

// ---------------- causal flash attention (fp16 mma, GQA) --------------------
#define FKR   136                         // halves per K/V smem row
#define FTILE (64 * FKR * 2)              // 17408 B
#define F_SMEM (4 * FTILE)                // K0,V0,K1,V1

__device__ __forceinline__ void f_fill(uint32_t sbase, int buf, int kt,
                                       const __half* __restrict__ kb,
                                       const __half* __restrict__ vb, int tid)
{
    const uint32_t kd = sbase + buf * (2 * FTILE);
    const uint32_t vd = kd + FTILE;
    const __half* kg = kb + (size_t)(kt * 64) * KVDIM;
    const __half* vg = vb + (size_t)(kt * 64) * KVDIM;
    #pragma unroll
    for (int j = 0; j < 8; j++) {
        int idx = tid + j * 128;
        int r = idx >> 4, c = idx & 15;
        cpasync16(kd + r * 272 + c * 16, kg + (size_t)r * KVDIM + c * 8);
        cpasync16(vd + r * 272 + c * 16, vg + (size_t)r * KVDIM + c * 8);
    }
    CP_COMMIT();
}

__global__ __launch_bounds__(128, 2)
void flash_h(const __half* __restrict__ q, const __half* __restrict__ k,
             const __half* __restrict__ v, __half* __restrict__ o)
{
    extern __shared__ char smem[];
    const uint32_t sbase = smem_u32(smem);
    const int tid = threadIdx.x, lane = tid & 31, w = tid >> 5;
    const int g = lane >> 2, tg = lane & 3;
    const int h = blockIdx.y;
    const int qt = gridDim.x - 1 - blockIdx.x;   // longest CTAs launch first
    const int q0 = qt * 64, khd = h >> 2;

    const __half* kb = k + khd * HD;
    const __half* vb = v + khd * HD;

    // ---- stage Q tile into buf1-K region (unused at kt=0) + overlap fill0
    {
        const __half* qg = q + (size_t)q0 * DIM + h * HD;
        const uint32_t qdst = sbase + 2 * FTILE;   // buf1 K region
        #pragma unroll
        for (int j = 0; j < 8; j++) {
            int idx = tid + j * 128;
            int r = idx >> 4, c = idx & 15;
            cpasync16(qdst + r * 272 + c * 16, qg + (size_t)r * DIM + c * 8);
        }
        CP_COMMIT();
    }
    f_fill(sbase, 0, 0, kb, vb, tid);   // overlap K/V tile 0 with Q load
    CP_WAIT(1);                          // Q group done (fill0 may be pending)
    __syncthreads();

    uint32_t qa[8][4];
    {
        const uint32_t qoff = sbase + 2 * FTILE
            + (uint32_t)((w * 16 + (lane & 15)) * 272 + (lane >> 4) * 16);
        #pragma unroll
        for (int ks = 0; ks < 8; ks++) ldsm4(qa[ks], qoff + ks * 32);
    }
    __syncthreads();   // Q frags read before buf1 can be refilled

    float m0 = -1e30f, m1 = -1e30f, l0 = 0.f, l1 = 0.f;
    float oacc[16][4];
    #pragma unroll
    for (int nf = 0; nf < 16; nf++)
        #pragma unroll
        for (int c = 0; c < 4; c++) oacc[nf][c] = 0.f;

    const uint32_t kboff = (uint32_t)(((lane & 7) + ((lane >> 4) << 3)) * 272
                                      + ((lane >> 3) & 1) * 16);
    const uint32_t vboff = (uint32_t)(((lane & 7) + ((lane >> 3) & 1) * 8) * 272
                                      + (lane >> 4) * 16);

    for (int kt = 0; kt <= qt; kt++) {
        if (kt < qt) {
            f_fill(sbase, (kt + 1) & 1, kt + 1, kb, vb, tid);
            CP_WAIT(1);
        } else {
            CP_WAIT(0);
        }
        __syncthreads();
        const uint32_t kbase = sbase + (kt & 1) * (2 * FTILE);
        const uint32_t vbase = kbase + FTILE;

        // ---- S = Q @ K^T
        float s[8][4];
        #pragma unroll
        for (int nf = 0; nf < 8; nf++)
            #pragma unroll
            for (int c = 0; c < 4; c++) s[nf][c] = 0.f;
        #pragma unroll
        for (int ks = 0; ks < 8; ks++) {
            #pragma unroll
            for (int nbp = 0; nbp < 4; nbp++) {
                uint32_t b[4];
                ldsm4(b, kbase + kboff + nbp * 16 * 272 + ks * 32);
                mma16(s[nbp * 2],     qa[ks], b[0], b[1]);
                mma16(s[nbp * 2 + 1], qa[ks], b[2], b[3]);
            }
        }

        // ---- causal mask on diagonal tile
        if (kt == qt) {
            int r0 = w * 16 + g, r1 = r0 + 8;
            #pragma unroll
            for (int nf = 0; nf < 8; nf++) {
                int c = nf * 8 + tg * 2;
                if (c     > r0) s[nf][0] = -1e30f;
                if (c + 1 > r0) s[nf][1] = -1e30f;
                if (c     > r1) s[nf][2] = -1e30f;
                if (c + 1 > r1) s[nf][3] = -1e30f;
            }
        }

        // ---- online softmax; P packed to fp16 registers
        float mx0 = -1e30f, mx1 = -1e30f;
        #pragma unroll
        for (int nf = 0; nf < 8; nf++) {
            mx0 = fmaxf(mx0, fmaxf(s[nf][0], s[nf][1]));
            mx1 = fmaxf(mx1, fmaxf(s[nf][2], s[nf][3]));
        }
        mx0 = fmaxf(mx0, __shfl_xor_sync(0xffffffffu, mx0, 1));
        mx0 = fmaxf(mx0, __shfl_xor_sync(0xffffffffu, mx0, 2));
        mx1 = fmaxf(mx1, __shfl_xor_sync(0xffffffffu, mx1, 1));
        mx1 = fmaxf(mx1, __shfl_xor_sync(0xffffffffu, mx1, 2));

        float mn0 = fmaxf(m0, mx0), mn1 = fmaxf(m1, mx1);
        float al0 = __expf(m0 - mn0), al1 = __expf(m1 - mn1);
        float rs0 = 0.f, rs1 = 0.f;
        uint32_t ph[8][2];
        #pragma unroll
        for (int nf = 0; nf < 8; nf++) {
            float p0 = __expf(s[nf][0] - mn0);
            float p1 = __expf(s[nf][1] - mn0);
            float p2 = __expf(s[nf][2] - mn1);
            float p3 = __expf(s[nf][3] - mn1);
            rs0 += p0 + p1; rs1 += p2 + p3;
            ph[nf][0] = f2h2(p0, p1);   // row g
            ph[nf][1] = f2h2(p2, p3);   // row g+8
        }
        rs0 += __shfl_xor_sync(0xffffffffu, rs0, 1);
        rs0 += __shfl_xor_sync(0xffffffffu, rs0, 2);
        rs1 += __shfl_xor_sync(0xffffffffu, rs1, 1);
        rs1 += __shfl_xor_sync(0xffffffffu, rs1, 2);
        l0 = l0 * al0 + rs0;  l1 = l1 * al1 + rs1;
        m0 = mn0;  m1 = mn1;
        #pragma unroll
        for (int nf = 0; nf < 16; nf++) {
            oacc[nf][0] *= al0; oacc[nf][1] *= al0;
            oacc[nf][2] *= al1; oacc[nf][3] *= al1;
        }

        // ---- O += P @ V   (V via ldmatrix.trans)
        #pragma unroll
        for (int ksv = 0; ksv < 4; ksv++) {
            uint32_t a[4];
            a[0] = ph[2 * ksv][0];     a[1] = ph[2 * ksv][1];
            a[2] = ph[2 * ksv + 1][0]; a[3] = ph[2 * ksv + 1][1];
            #pragma unroll
            for (int nbp = 0; nbp < 8; nbp++) {
                uint32_t b[4];
                ldsm4t(b, vbase + vboff + ksv * 16 * 272 + nbp * 32);
                mma16(oacc[nbp * 2],     a, b[0], b[1]);
                mma16(oacc[nbp * 2 + 1], a, b[2], b[3]);
            }
        }
        __syncthreads();   // all warps done with this buffer before refill
    }

    // ---- epilogue: fp16 store (A operand of the wo GEMM)
    float inv0 = 1.f / l0, inv1 = 1.f / l1;
    __half* o0 = o + (size_t)(q0 + w * 16 + g) * DIM + h * HD;
    __half* o1 = o0 + (size_t)8 * DIM;
    #pragma unroll
    for (int nf = 0; nf < 16; nf++) {
        *(uint32_t*)&o0[nf * 8 + tg * 2] = f2h2(oacc[nf][0] * inv0, oacc[nf][1] * inv0);
        *(uint32_t*)&o1[nf * 8 + tg * 2] = f2h2(oacc[nf][2] * inv1, oacc[nf][3] * inv1);
    }
}

// ---------------- launch ------------------------------------------------------
extern "C" void kernel_launch(void* const* d_in, const int* in_sizes, int n_in,
                              void* d_out, int out_size)
{
    const float* x  = (const float*)d_in[0];
    // d_in[1] = cache_kv: unused (start_pos==0 => cache is pass-through)
    const float* fr = (const float*)d_in[2];
    const float* wq = (const float*)d_in[3];
    const float* wk = (const float*)d_in[4];
    const float* wv = (const float*)d_in[5];
    const float* wo = (const float*)d_in[6];
    float* out = (float*)d_out;

    __half *pxh, *pqh, *pkh, *pvh, *pah, *pwq, *pwk, *pwv, *pwo;
    cudaGetSymbolAddress((void**)&pxh, g_xh);
    cudaGetSymbolAddress((void**)&pqh, g_qh);
    cudaGetSymbolAddress((void**)&pkh, g_kh);
    cudaGetSymbolAddress((void**)&pvh, g_vh);
    cudaGetSymbolAddress((void**)&pah, g_ah);
    cudaGetSymbolAddress((void**)&pwq, g_wqh);
    cudaGetSymbolAddress((void**)&pwk, g_wkh);
    cudaGetSymbolAddress((void**)&pwv, g_wvh);
    cudaGetSymbolAddress((void**)&pwo, g_woh);

    cudaFuncSetAttribute((gemm_h<__half, 1>),
                         cudaFuncAttributeMaxDynamicSharedMemorySize, G_SMEM);
    cudaFuncSetAttribute((gemm_h<__half, 2>),
                         cudaFuncAttributeMaxDynamicSharedMemorySize, G_SMEM);
    cudaFuncSetAttribute((gemm_h<__half, 0>),
                         cudaFuncAttributeMaxDynamicSharedMemorySize, G_SMEM);
    cudaFuncSetAttribute((gemm_h<float, 0>),
                         cudaFuncAttributeMaxDynamicSharedMemorySize, G_SMEM);
    cudaFuncSetAttribute(flash_h,
                         cudaFuncAttributeMaxDynamicSharedMemorySize, F_SMEM);

    // --- pre-passes: fp16 conversion (+ weight transpose to [N][K]) ---
    conv_half4<<<(SEQ * DIM / 4 + 255) / 256, 256>>>(x, pxh, SEQ * DIM / 4);
    dim3 tb(32, 8);
    transpose_h<<<dim3(DIM / 32,   DIM / 32), tb>>>(wq, pwq, DIM, DIM);
    transpose_h<<<dim3(KVDIM / 32, DIM / 32), tb>>>(wk, pwk, DIM, KVDIM);
    transpose_h<<<dim3(KVDIM / 32, DIM / 32), tb>>>(wv, pwv, DIM, KVDIM);
    transpose_h<<<dim3(DIM / 32,   DIM / 32), tb>>>(wo, pwo, DIM, DIM);

    // --- QKV projections; RoPE fused into Q/K epilogues, all fp16 out ---
    gemm_h<__half, 1><<<dim3(DIM / 128,   SEQ / 128), 256, G_SMEM>>>(pxh, pwq, pqh, fr, DIM,   DIM);
    gemm_h<__half, 2><<<dim3(KVDIM / 128, SEQ / 128), 256, G_SMEM>>>(pxh, pwk, pkh, fr, KVDIM, DIM);
    gemm_h<__half, 0><<<dim3(KVDIM / 128, SEQ / 128), 256, G_SMEM>>>(pxh, pwv, pvh, fr, KVDIM, DIM);

    // --- causal GQA flash attention (fp16 mma) ---
    flash_h<<<dim3(SEQ / 64, NH), 128, F_SMEM>>>(pqh, pkh, pvh, pah);

    // --- output projection ---
    gemm_h<float, 0><<<dim3(DIM / 128, SEQ / 128), 256, G_SMEM>>>(pah, pwo, out, fr, DIM, DIM);
}

// round 12
// speedup vs baseline: 1.1481x; 1.0448x over previous
#include <cuda_runtime.h>
#include <cuda_fp16.h>
#include <cstdint>

#define SEQ   2048
#define DIM   4096
#define NH    32
#define NKV   8
#define HD    128
#define KVDIM 1024   // NKV*HD
#define NQKV  (DIM + 2 * KVDIM)   // 6144 fused QKV output columns

// ---------------- scratch (static device globals; no allocations) ----------
__device__ __half g_xh[SEQ * DIM];       // x fp16
__device__ __half g_qh[SEQ * DIM];       // roped+scaled q fp16 (GEMM epilogue)
__device__ __half g_kh[SEQ * KVDIM];     // roped k fp16 (GEMM epilogue)
__device__ __half g_vh[SEQ * KVDIM];     // v fp16 (direct GEMM output)
__device__ __half g_ah[SEQ * DIM];       // attention out fp16
__device__ __half g_wh[NQKV * DIM];      // concat(wq^T, wk^T, wv^T) [6144][4096]
__device__ __half g_woh[DIM * DIM];      // wo^T

// ---------------- PTX helpers ----------------------------------------------
__device__ __forceinline__ uint32_t smem_u32(const void* p) {
    uint32_t a;
    asm("{ .reg .u64 t; cvta.to.shared.u64 t, %1; cvt.u32.u64 %0, t; }"
        : "=r"(a) : "l"(p));
    return a;
}
__device__ __forceinline__ void cpasync16(uint32_t dst, const void* src) {
    asm volatile("cp.async.cg.shared.global [%0], [%1], 16;" :: "r"(dst), "l"(src));
}
#define CP_COMMIT() asm volatile("cp.async.commit_group;" ::: "memory")
#define CP_WAIT(N)  asm volatile("cp.async.wait_group %0;" :: "n"(N) : "memory")

__device__ __forceinline__ void ldsm4(uint32_t* r, uint32_t a) {
    asm volatile("ldmatrix.sync.aligned.m8n8.x4.shared.b16 {%0,%1,%2,%3}, [%4];"
        : "=r"(r[0]), "=r"(r[1]), "=r"(r[2]), "=r"(r[3]) : "r"(a));
}
__device__ __forceinline__ void ldsm4t(uint32_t* r, uint32_t a) {
    asm volatile("ldmatrix.sync.aligned.m8n8.x4.trans.shared.b16 {%0,%1,%2,%3}, [%4];"
        : "=r"(r[0]), "=r"(r[1]), "=r"(r[2]), "=r"(r[3]) : "r"(a));
}
// D += A(16x16) * B(16x8), fp16 in, fp32 accum
__device__ __forceinline__ void mma16(float* c, const uint32_t* a,
                                      uint32_t b0, uint32_t b1) {
    asm volatile(
        "mma.sync.aligned.m16n8k16.row.col.f32.f16.f16.f32 "
        "{%0,%1,%2,%3}, {%4,%5,%6,%7}, {%8,%9}, {%0,%1,%2,%3};"
        : "+f"(c[0]), "+f"(c[1]), "+f"(c[2]), "+f"(c[3])
        : "r"(a[0]), "r"(a[1]), "r"(a[2]), "r"(a[3]), "r"(b0), "r"(b1));
}
__device__ __forceinline__ uint32_t f2h2(float lo, float hi) {
    uint32_t d;
    asm("cvt.rn.f16x2.f32 %0, %1, %2;" : "=r"(d) : "f"(hi), "f"(lo));
    return d;
}

// ---------------- fp16 GEMM: C[M,N] = A[M,K] @ BT[N,K]^T --------------------
// 128x128x32 CTA tile, 256 threads (8 warps 2x4, warp tile 64x32), 4-stage
// cp.async pipeline, 2 CTAs/SM.
// RMODE: 0 = plain store to C; 3 = fused-QKV routing epilogue (column region
// selects Q rope+scale / K rope / V plain; regions are 128-aligned so the
// branch is CTA-uniform).
#define G_STAGE 20480             // A 128*80 + B 128*80
#define G_SMEM  (4 * G_STAGE)     // 81920 B -> 2 CTAs/SM

__device__ __forceinline__ void g_fill(uint32_t sbase, int slot,
                                       const __half* __restrict__ Ab,
                                       const __half* __restrict__ Bb,
                                       int K, int kt, int tid)
{
    const uint32_t sA = sbase + slot * G_STAGE;
    const uint32_t sB = sA + 10240;
    const __half* ag = Ab + (size_t)kt * 32;
    const __half* bg = Bb + (size_t)kt * 32;
    #pragma unroll
    for (int j = 0; j < 2; j++) {
        int idx = tid + j * 256;
        int r = idx >> 2, c = idx & 3;
        cpasync16(sA + r * 80 + c * 16, ag + (size_t)r * K + c * 8);
        cpasync16(sB + r * 80 + c * 16, bg + (size_t)r * K + c * 8);
    }
    CP_COMMIT();
}

template <typename OutT, int RMODE>
__global__ __launch_bounds__(256, 2)
void gemm_h(const __half* __restrict__ A, const __half* __restrict__ BT,
            OutT* __restrict__ C, const float* __restrict__ fr, int N, int K)
{
    extern __shared__ char smem[];
    const uint32_t sbase = smem_u32(smem);
    const int tid = threadIdx.x, lane = tid & 31, wid = tid >> 5;
    const int g = lane >> 2, tg = lane & 3;
    const int wm = (wid & 1) * 64, wn = (wid >> 1) * 32;
    const int rowBase = blockIdx.y * 128, colBase = blockIdx.x * 128;

    const __half* Ab = A  + (size_t)rowBase * K;
    const __half* Bb = BT + (size_t)colBase * K;
    const int T = K / 32;

    const uint32_t aoff = (uint32_t)((wm + (lane & 15)) * 80 + (lane >> 4) * 16);
    const uint32_t boff = (uint32_t)((wn + (lane & 7) + ((lane >> 4) << 3)) * 80
                                     + ((lane >> 3) & 1) * 16);

    float acc[4][4][4];
    #pragma unroll
    for (int mi = 0; mi < 4; mi++)
        #pragma unroll
        for (int ni = 0; ni < 4; ni++)
            #pragma unroll
            for (int c = 0; c < 4; c++) acc[mi][ni][c] = 0.f;

    #pragma unroll
    for (int s = 0; s < 3; s++) g_fill(sbase, s, Ab, Bb, K, s, tid);

    for (int t = 0; t < T; t++) {
        CP_WAIT(2);
        __syncthreads();
        const uint32_t sA = sbase + (t & 3) * G_STAGE;
        const uint32_t sB = sA + 10240;
        #pragma unroll
        for (int ks = 0; ks < 2; ks++) {
            uint32_t a[4][4], b[2][4];
            #pragma unroll
            for (int mi = 0; mi < 4; mi++)
                ldsm4(a[mi], sA + aoff + mi * 1280 + ks * 32);
            #pragma unroll
            for (int nbp = 0; nbp < 2; nbp++)
                ldsm4(b[nbp], sB + boff + nbp * 1280 + ks * 32);
            #pragma unroll
            for (int mi = 0; mi < 4; mi++) {
                mma16(acc[mi][0], a[mi], b[0][0], b[0][1]);
                mma16(acc[mi][1], a[mi], b[0][2], b[0][3]);
                mma16(acc[mi][2], a[mi], b[1][0], b[1][1]);
                mma16(acc[mi][3], a[mi], b[1][2], b[1][3]);
            }
        }
        if (t + 3 < T) g_fill(sbase, (t + 3) & 3, Ab, Bb, K, t + 3, tid);
        else           CP_COMMIT();   // keep wait_group accounting uniform
    }

    const float scale = 0.08838834764831845f;   // 1/sqrt(128)
    #pragma unroll
    for (int mi = 0; mi < 4; mi++) {
        #pragma unroll
        for (int ni = 0; ni < 4; ni++) {
            int r0 = rowBase + wm + mi * 16 + g;
            int r1 = r0 + 8;
            int cc = colBase + wn + ni * 8 + tg * 2;
            float v0 = acc[mi][ni][0], v1 = acc[mi][ni][1];
            float v2 = acc[mi][ni][2], v3 = acc[mi][ni][3];
            if (RMODE == 3) {
                // fused QKV routing; rope for Q/K regions
                if (cc < DIM + KVDIM) {
                    int fd = cc & (HD - 1);
                    float2 f0 = *(const float2*)&fr[(size_t)r0 * HD + fd];
                    float2 f1 = *(const float2*)&fr[(size_t)r1 * HD + fd];
                    float t0 = v0 * f0.x - v1 * f0.y;
                    float t1 = v0 * f0.y + v1 * f0.x;
                    float t2 = v2 * f1.x - v3 * f1.y;
                    float t3 = v2 * f1.y + v3 * f1.x;
                    if (cc < DIM) { t0 *= scale; t1 *= scale; t2 *= scale; t3 *= scale; }
                    v0 = t0; v1 = t1; v2 = t2; v3 = t3;
                }
                if (cc < DIM) {
                    *(uint32_t*)&g_qh[(size_t)r0 * DIM + cc] = f2h2(v0, v1);
                    *(uint32_t*)&g_qh[(size_t)r1 * DIM + cc] = f2h2(v2, v3);
                } else if (cc < DIM + KVDIM) {
                    int c2 = cc - DIM;
                    *(uint32_t*)&g_kh[(size_t)r0 * KVDIM + c2] = f2h2(v0, v1);
                    *(uint32_t*)&g_kh[(size_t)r1 * KVDIM + c2] = f2h2(v2, v3);
                } else {
                    int c2 = cc - DIM - KVDIM;
                    *(uint32_t*)&g_vh[(size_t)r0 * KVDIM + c2] = f2h2(v0, v1);
                    *(uint32_t*)&g_vh[(size_t)r1 * KVDIM + c2] = f2h2(v2, v3);
                }
            } else {
                if (sizeof(OutT) == 4) {
                    float2 t0; t0.x = v0; t0.y = v1;
                    float2 t1; t1.x = v2; t1.y = v3;
                    *(float2*)&((float*)C)[(size_t)r0 * N + cc] = t0;
                    *(float2*)&((float*)C)[(size_t)r1 * N + cc] = t1;
                } else {
                    *(uint32_t*)&((__half*)C)[(size_t)r0 * N + cc] = f2h2(v0, v1);
                    *(uint32_t*)&((__half*)C)[(size_t)r1 * N + cc] = f2h2(v2, v3);
                }
            }
        }
    }
}

// ---------------- pre-passes -------------------------------------------------
__global__ void conv_half4(const float* __restrict__ in, __half* __restrict__ out,
                           int n4)
{
    int i = blockIdx.x * blockDim.x + threadIdx.x;
    if (i >= n4) return;
    float4 v = ((const float4*)in)[i];
    uint2 o;
    o.x = f2h2(v.x, v.y);
    o.y = f2h2(v.z, v.w);
    ((uint2*)out)[i] = o;
}

// W[K][N] fp32 row-major -> WT[N][K] fp16 row-major. 64x32 tiles; packed
// fp16x2 stores (4B/lane, 128B/warp contiguous).
__global__ void transpose_h(const float* __restrict__ W, __half* __restrict__ WT,
                            int K, int N)
{
    __shared__ float t[64][33];
    int x  = blockIdx.x * 32 + threadIdx.x;   // n
    int y0 = blockIdx.y * 64;                 // k base
    #pragma unroll
    for (int j = threadIdx.y; j < 64; j += 8)
        t[j][threadIdx.x] = W[(size_t)(y0 + j) * N + x];
    __syncthreads();
    int n0 = blockIdx.x * 32;
    int kk = threadIdx.x * 2;                 // local k pair
    #pragma unroll
    for (int j = threadIdx.y; j < 32; j += 8) {
        uint32_t v = f2h2(t[kk][j], t[kk + 1][j]);
        *(uint32_t*)&WT[(size_t)(n0 + j) * K + y0 + kk] = v;
    }
}

// ---------------- causal flash attention (fp16 mma, GQA) --------------------
#define FKR   136                         // halves per K/V smem row
#define FTILE (64 * FKR * 2)              // 17408 B
#define F_SMEM (4 * FTILE)                // K0,V0,K1,V1

__device__ __forceinline__ void f_fill(uint32_t sbase, int buf, int kt,
                                       const __half* __restrict__ kb,
                                       const __half* __restrict__ vb, int tid)
{
    const uint32_t kd = sbase + buf * (2 * FTILE);
    const uint32_t vd = kd + FTILE;
    const __half* kg = kb + (size_t)(kt * 64) * KVDIM;
    const __half* vg = vb + (size_t)(kt * 64) * KVDIM;
    #pragma unroll
    for (int j = 0; j < 8; j++) {
        int idx = tid + j * 128;
        int r = idx >> 4, c = idx & 15;
        cpasync16(kd + r * 272 + c * 16, kg + (size_t)r * KVDIM + c * 8);
        cpasync16(vd + r * 272 + c * 16, vg + (size_t)r * KVDIM + c * 8);
    }
    CP_COMMIT();
}

__global__ __launch_bounds__(128, 2)
void flash_h(const __half* __restrict__ q, const __half* __restrict__ k,
             const __half* __restrict__ v, __half* __restrict__ o)
{
    extern __shared__ char smem[];
    const uint32_t sbase = smem_u32(smem);
    const int tid = threadIdx.x, lane = tid & 31, w = tid >> 5;
    const int g = lane >> 2, tg = lane & 3;
    const int h = blockIdx.y;
    const int qt = gridDim.x - 1 - blockIdx.x;   // longest CTAs launch first
    const int q0 = qt * 64, khd = h >> 2;

    const __half* kb = k + khd * HD;
    const __half* vb = v + khd * HD;

    // ---- stage Q tile into buf1-K region (unused at kt=0) + overlap fill0
    {
        const __half* qg = q + (size_t)q0 * DIM + h * HD;
        const uint32_t qdst = sbase + 2 * FTILE;   // buf1 K region
        #pragma unroll
        for (int j = 0; j < 8; j++) {
            int idx = tid + j * 128;
            int r = idx >> 4, c = idx & 15;
            cpasync16(qdst + r * 272 + c * 16, qg + (size_t)r * DIM + c * 8);
        }
        CP_COMMIT();
    }
    f_fill(sbase, 0, 0, kb, vb, tid);   // overlap K/V tile 0 with Q load
    CP_WAIT(1);                          // Q group done (fill0 may be pending)
    __syncthreads();

    uint32_t qa[8][4];
    {
        const uint32_t qoff = sbase + 2 * FTILE
            + (uint32_t)((w * 16 + (lane & 15)) * 272 + (lane >> 4) * 16);
        #pragma unroll
        for (int ks = 0; ks < 8; ks++) ldsm4(qa[ks], qoff + ks * 32);
    }
    __syncthreads();   // Q frags read before buf1 can be refilled

    float m0 = -1e30f, m1 = -1e30f, l0 = 0.f, l1 = 0.f;
    float oacc[16][4];
    #pragma unroll
    for (int nf = 0; nf < 16; nf++)
        #pragma unroll
        for (int c = 0; c < 4; c++) oacc[nf][c] = 0.f;

    const uint32_t kboff = (uint32_t)(((lane & 7) + ((lane >> 4) << 3)) * 272
                                      + ((lane >> 3) & 1) * 16);
    const uint32_t vboff = (uint32_t)(((lane & 7) + ((lane >> 3) & 1) * 8) * 272
                                      + (lane >> 4) * 16);

    for (int kt = 0; kt <= qt; kt++) {
        if (kt < qt) {
            f_fill(sbase, (kt + 1) & 1, kt + 1, kb, vb, tid);
            CP_WAIT(1);
        } else {
            CP_WAIT(0);
        }
        __syncthreads();
        const uint32_t kbase = sbase + (kt & 1) * (2 * FTILE);
        const uint32_t vbase = kbase + FTILE;

        // ---- S = Q @ K^T
        float s[8][4];
        #pragma unroll
        for (int nf = 0; nf < 8; nf++)
            #pragma unroll
            for (int c = 0; c < 4; c++) s[nf][c] = 0.f;
        #pragma unroll
        for (int ks = 0; ks < 8; ks++) {
            #pragma unroll
            for (int nbp = 0; nbp < 4; nbp++) {
                uint32_t b[4];
                ldsm4(b, kbase + kboff + nbp * 16 * 272 + ks * 32);
                mma16(s[nbp * 2],     qa[ks], b[0], b[1]);
                mma16(s[nbp * 2 + 1], qa[ks], b[2], b[3]);
            }
        }

        // ---- causal mask on diagonal tile
        if (kt == qt) {
            int r0 = w * 16 + g, r1 = r0 + 8;
            #pragma unroll
            for (int nf = 0; nf < 8; nf++) {
                int c = nf * 8 + tg * 2;
                if (c     > r0) s[nf][0] = -1e30f;
                if (c + 1 > r0) s[nf][1] = -1e30f;
                if (c     > r1) s[nf][2] = -1e30f;
                if (c + 1 > r1) s[nf][3] = -1e30f;
            }
        }

        // ---- online softmax; P packed to fp16 registers
        float mx0 = -1e30f, mx1 = -1e30f;
        #pragma unroll
        for (int nf = 0; nf < 8; nf++) {
            mx0 = fmaxf(mx0, fmaxf(s[nf][0], s[nf][1]));
            mx1 = fmaxf(mx1, fmaxf(s[nf][2], s[nf][3]));
        }
        mx0 = fmaxf(mx0, __shfl_xor_sync(0xffffffffu, mx0, 1));
        mx0 = fmaxf(mx0, __shfl_xor_sync(0xffffffffu, mx0, 2));
        mx1 = fmaxf(mx1, __shfl_xor_sync(0xffffffffu, mx1, 1));
        mx1 = fmaxf(mx1, __shfl_xor_sync(0xffffffffu, mx1, 2));

        float mn0 = fmaxf(m0, mx0), mn1 = fmaxf(m1, mx1);
        float al0 = __expf(m0 - mn0), al1 = __expf(m1 - mn1);
        float rs0 = 0.f, rs1 = 0.f;
        uint32_t ph[8][2];
        #pragma unroll
        for (int nf = 0; nf < 8; nf++) {
            float p0 = __expf(s[nf][0] - mn0);
            float p1 = __expf(s[nf][1] - mn0);
            float p2 = __expf(s[nf][2] - mn1);
            float p3 = __expf(s[nf][3] - mn1);
            rs0 += p0 + p1; rs1 += p2 + p3;
            ph[nf][0] = f2h2(p0, p1);   // row g
            ph[nf][1] = f2h2(p2, p3);   // row g+8
        }
        rs0 += __shfl_xor_sync(0xffffffffu, rs0, 1);
        rs0 += __shfl_xor_sync(0xffffffffu, rs0, 2);
        rs1 += __shfl_xor_sync(0xffffffffu, rs1, 1);
        rs1 += __shfl_xor_sync(0xffffffffu, rs1, 2);
        l0 = l0 * al0 + rs0;  l1 = l1 * al1 + rs1;
        m0 = mn0;  m1 = mn1;
        #pragma unroll
        for (int nf = 0; nf < 16; nf++) {
            oacc[nf][0] *= al0; oacc[nf][1] *= al0;
            oacc[nf][2] *= al1; oacc[nf][3] *= al1;
        }

        // ---- O += P @ V   (V via ldmatrix.trans)
        #pragma unroll
        for (int ksv = 0; ksv < 4; ksv++) {
            uint32_t a[4];
            a[0] = ph[2 * ksv][0];     a[1] = ph[2 * ksv][1];
            a[2] = ph[2 * ksv + 1][0]; a[3] = ph[2 * ksv + 1][1];
            #pragma unroll
            for (int nbp = 0; nbp < 8; nbp++) {
                uint32_t b[4];
                ldsm4t(b, vbase + vboff + ksv * 16 * 272 + nbp * 32);
                mma16(oacc[nbp * 2],     a, b[0], b[1]);
                mma16(oacc[nbp * 2 + 1], a, b[2], b[3]);
            }
        }
        __syncthreads();   // all warps done with this buffer before refill
    }

    // ---- epilogue: fp16 store (A operand of the wo GEMM)
    float inv0 = 1.f / l0, inv1 = 1.f / l1;
    __half* o0 = o + (size_t)(q0 + w * 16 + g) * DIM + h * HD;
    __half* o1 = o0 + (size_t)8 * DIM;
    #pragma unroll
    for (int nf = 0; nf < 16; nf++) {
        *(uint32_t*)&o0[nf * 8 + tg * 2] = f2h2(oacc[nf][0] * inv0, oacc[nf][1] * inv0);
        *(uint32_t*)&o1[nf * 8 + tg * 2] = f2h2(oacc[nf][2] * inv1, oacc[nf][3] * inv1);
    }
}

// ---------------- launch ------------------------------------------------------
extern "C" void kernel_launch(void* const* d_in, const int* in_sizes, int n_in,
                              void* d_out, int out_size)
{
    const float* x  = (const float*)d_in[0];
    // d_in[1] = cache_kv: unused (start_pos==0 => cache is pass-through)
    const float* fr = (const float*)d_in[2];
    const float* wq = (const float*)d_in[3];
    const float* wk = (const float*)d_in[4];
    const float* wv = (const float*)d_in[5];
    const float* wo = (const float*)d_in[6];
    float* out = (float*)d_out;

    __half *pxh, *pqh, *pkh, *pvh, *pah, *pwh, *pwoh;
    cudaGetSymbolAddress((void**)&pxh,  g_xh);
    cudaGetSymbolAddress((void**)&pqh,  g_qh);
    cudaGetSymbolAddress((void**)&pkh,  g_kh);
    cudaGetSymbolAddress((void**)&pvh,  g_vh);
    cudaGetSymbolAddress((void**)&pah,  g_ah);
    cudaGetSymbolAddress((void**)&pwh,  g_wh);
    cudaGetSymbolAddress((void**)&pwoh, g_woh);

    cudaFuncSetAttribute((gemm_h<__half, 3>),
                         cudaFuncAttributeMaxDynamicSharedMemorySize, G_SMEM);
    cudaFuncSetAttribute((gemm_h<float, 0>),
                         cudaFuncAttributeMaxDynamicSharedMemorySize, G_SMEM);
    cudaFuncSetAttribute(flash_h,
                         cudaFuncAttributeMaxDynamicSharedMemorySize, F_SMEM);

    // --- pre-passes: x fp16 conversion + weight transposes into concat buf ---
    conv_half4<<<(SEQ * DIM / 4 + 255) / 256, 256>>>(x, pxh, SEQ * DIM / 4);
    dim3 tb(32, 8);
    transpose_h<<<dim3(DIM / 32,   DIM / 64), tb>>>(wq, pwh, DIM, DIM);
    transpose_h<<<dim3(KVDIM / 32, DIM / 64), tb>>>(wk, pwh + (size_t)DIM * DIM, DIM, KVDIM);
    transpose_h<<<dim3(KVDIM / 32, DIM / 64), tb>>>(wv, pwh + (size_t)(DIM + KVDIM) * DIM, DIM, KVDIM);
    transpose_h<<<dim3(DIM / 32,   DIM / 64), tb>>>(wo, pwoh, DIM, DIM);

    // --- fused QKV projection (one launch; rope/scale/routing in epilogue) ---
    gemm_h<__half, 3><<<dim3(NQKV / 128, SEQ / 128), 256, G_SMEM>>>(
        pxh, pwh, pqh /*unused*/, fr, NQKV, DIM);

    // --- causal GQA flash attention (fp16 mma) ---
    flash_h<<<dim3(SEQ / 64, NH), 128, F_SMEM>>>(pqh, pkh, pvh, pah);

    // --- output projection ---
    gemm_h<float, 0><<<dim3(DIM / 128, SEQ / 128), 256, G_SMEM>>>(
        pah, pwoh, out, fr, DIM, DIM);
}

// round 15
// speedup vs baseline: 1.2121x; 1.0558x over previous
#include <cuda_runtime.h>
#include <cuda_fp16.h>
#include <cstdint>

#define SEQ   2048
#define DIM   4096
#define NH    32
#define NKV   8
#define HD    128
#define KVDIM 1024   // NKV*HD
#define NQKV  (DIM + 2 * KVDIM)   // 6144 fused QKV output columns

// ---------------- scratch (static device globals; no allocations) ----------
__device__ __half g_xh[SEQ * DIM];       // x fp16
__device__ __half g_qh[SEQ * DIM];       // roped+scaled q fp16 (GEMM epilogue)
__device__ __half g_kh[SEQ * KVDIM];     // roped k fp16 (GEMM epilogue)
__device__ __half g_vh[SEQ * KVDIM];     // v fp16 (direct GEMM output)
__device__ __half g_ah[SEQ * DIM];       // attention out fp16
__device__ __half g_wh[NQKV * DIM];      // concat(wq^T, wk^T, wv^T) [6144][4096]
__device__ __half g_woh[DIM * DIM];      // wo^T

// ---------------- PTX helpers ----------------------------------------------
__device__ __forceinline__ uint32_t smem_u32(const void* p) {
    uint32_t a;
    asm("{ .reg .u64 t; cvta.to.shared.u64 t, %1; cvt.u32.u64 %0, t; }"
        : "=r"(a) : "l"(p));
    return a;
}
__device__ __forceinline__ void cpasync16(uint32_t dst, const void* src) {
    asm volatile("cp.async.cg.shared.global [%0], [%1], 16;" :: "r"(dst), "l"(src));
}
#define CP_COMMIT() asm volatile("cp.async.commit_group;" ::: "memory")
#define CP_WAIT(N)  asm volatile("cp.async.wait_group %0;" :: "n"(N) : "memory")

__device__ __forceinline__ void ldsm4(uint32_t* r, uint32_t a) {
    asm volatile("ldmatrix.sync.aligned.m8n8.x4.shared.b16 {%0,%1,%2,%3}, [%4];"
        : "=r"(r[0]), "=r"(r[1]), "=r"(r[2]), "=r"(r[3]) : "r"(a));
}
__device__ __forceinline__ void ldsm4t(uint32_t* r, uint32_t a) {
    asm volatile("ldmatrix.sync.aligned.m8n8.x4.trans.shared.b16 {%0,%1,%2,%3}, [%4];"
        : "=r"(r[0]), "=r"(r[1]), "=r"(r[2]), "=r"(r[3]) : "r"(a));
}
// D += A(16x16) * B(16x8), fp16 in, fp32 accum
__device__ __forceinline__ void mma16(float* c, const uint32_t* a,
                                      uint32_t b0, uint32_t b1) {
    asm volatile(
        "mma.sync.aligned.m16n8k16.row.col.f32.f16.f16.f32 "
        "{%0,%1,%2,%3}, {%4,%5,%6,%7}, {%8,%9}, {%0,%1,%2,%3};"
        : "+f"(c[0]), "+f"(c[1]), "+f"(c[2]), "+f"(c[3])
        : "r"(a[0]), "r"(a[1]), "r"(a[2]), "r"(a[3]), "r"(b0), "r"(b1));
}
__device__ __forceinline__ uint32_t f2h2(float lo, float hi) {
    uint32_t d;
    asm("cvt.rn.f16x2.f32 %0, %1, %2;" : "=r"(d) : "f"(hi), "f"(lo));
    return d;
}

// ---------------- fp16 GEMM: C[M,N] = A[M,K] @ BT[N,K]^T --------------------
// 128x128x32 CTA tile, 256 threads (8 warps 2x4, warp tile 64x32), 4-stage
// cp.async pipeline, 2 CTAs/SM.
// RMODE: 0 = plain store to C; 3 = fused-QKV routing epilogue (column region
// selects Q rope+scale / K rope / V plain; regions are 128-aligned so the
// branch is CTA-uniform).
#define G_STAGE 20480             // A 128*80 + B 128*80
#define G_SMEM  (4 * G_STAGE)     // 81920 B -> 2 CTAs/SM

__device__ __forceinline__ void g_fill(uint32_t sbase, int slot,
                                       const __half* __restrict__ Ab,
                                       const __half* __restrict__ Bb,
                                       int K, int kt, int tid)
{
    const uint32_t sA = sbase + slot * G_STAGE;
    const uint32_t sB = sA + 10240;
    const __half* ag = Ab + (size_t)kt * 32;
    const __half* bg = Bb + (size_t)kt * 32;
    #pragma unroll
    for (int j = 0; j < 2; j++) {
        int idx = tid + j * 256;
        int r = idx >> 2, c = idx & 3;
        cpasync16(sA + r * 80 + c * 16, ag + (size_t)r * K + c * 8);
        cpasync16(sB + r * 80 + c * 16, bg + (size_t)r * K + c * 8);
    }
    CP_COMMIT();
}

template <typename OutT, int RMODE>
__global__ __launch_bounds__(256, 2)
void gemm_h(const __half* __restrict__ A, const __half* __restrict__ BT,
            OutT* __restrict__ C, const float* __restrict__ fr, int N, int K)
{
    extern __shared__ char smem[];
    const uint32_t sbase = smem_u32(smem);
    const int tid = threadIdx.x, lane = tid & 31, wid = tid >> 5;
    const int g = lane >> 2, tg = lane & 3;
    const int wm = (wid & 1) * 64, wn = (wid >> 1) * 32;
    const int rowBase = blockIdx.y * 128, colBase = blockIdx.x * 128;

    const __half* Ab = A  + (size_t)rowBase * K;
    const __half* Bb = BT + (size_t)colBase * K;
    const int T = K / 32;

    const uint32_t aoff = (uint32_t)((wm + (lane & 15)) * 80 + (lane >> 4) * 16);
    const uint32_t boff = (uint32_t)((wn + (lane & 7) + ((lane >> 4) << 3)) * 80
                                     + ((lane >> 3) & 1) * 16);

    float acc[4][4][4];
    #pragma unroll
    for (int mi = 0; mi < 4; mi++)
        #pragma unroll
        for (int ni = 0; ni < 4; ni++)
            #pragma unroll
            for (int c = 0; c < 4; c++) acc[mi][ni][c] = 0.f;

    #pragma unroll
    for (int s = 0; s < 3; s++) g_fill(sbase, s, Ab, Bb, K, s, tid);

    for (int t = 0; t < T; t++) {
        CP_WAIT(2);
        __syncthreads();
        const uint32_t sA = sbase + (t & 3) * G_STAGE;
        const uint32_t sB = sA + 10240;
        #pragma unroll
        for (int ks = 0; ks < 2; ks++) {
            uint32_t a[4][4], b[2][4];
            #pragma unroll
            for (int mi = 0; mi < 4; mi++)
                ldsm4(a[mi], sA + aoff + mi * 1280 + ks * 32);
            #pragma unroll
            for (int nbp = 0; nbp < 2; nbp++)
                ldsm4(b[nbp], sB + boff + nbp * 1280 + ks * 32);
            #pragma unroll
            for (int mi = 0; mi < 4; mi++) {
                mma16(acc[mi][0], a[mi], b[0][0], b[0][1]);
                mma16(acc[mi][1], a[mi], b[0][2], b[0][3]);
                mma16(acc[mi][2], a[mi], b[1][0], b[1][1]);
                mma16(acc[mi][3], a[mi], b[1][2], b[1][3]);
            }
        }
        if (t + 3 < T) g_fill(sbase, (t + 3) & 3, Ab, Bb, K, t + 3, tid);
        else           CP_COMMIT();   // keep wait_group accounting uniform
    }

    const float scale = 0.08838834764831845f;   // 1/sqrt(128)
    #pragma unroll
    for (int mi = 0; mi < 4; mi++) {
        #pragma unroll
        for (int ni = 0; ni < 4; ni++) {
            int r0 = rowBase + wm + mi * 16 + g;
            int r1 = r0 + 8;
            int cc = colBase + wn + ni * 8 + tg * 2;
            float v0 = acc[mi][ni][0], v1 = acc[mi][ni][1];
            float v2 = acc[mi][ni][2], v3 = acc[mi][ni][3];
            if (RMODE == 3) {
                // fused QKV routing; rope for Q/K regions
                if (cc < DIM + KVDIM) {
                    int fd = cc & (HD - 1);
                    float2 f0 = *(const float2*)&fr[(size_t)r0 * HD + fd];
                    float2 f1 = *(const float2*)&fr[(size_t)r1 * HD + fd];
                    float t0 = v0 * f0.x - v1 * f0.y;
                    float t1 = v0 * f0.y + v1 * f0.x;
                    float t2 = v2 * f1.x - v3 * f1.y;
                    float t3 = v2 * f1.y + v3 * f1.x;
                    if (cc < DIM) { t0 *= scale; t1 *= scale; t2 *= scale; t3 *= scale; }
                    v0 = t0; v1 = t1; v2 = t2; v3 = t3;
                }
                if (cc < DIM) {
                    *(uint32_t*)&g_qh[(size_t)r0 * DIM + cc] = f2h2(v0, v1);
                    *(uint32_t*)&g_qh[(size_t)r1 * DIM + cc] = f2h2(v2, v3);
                } else if (cc < DIM + KVDIM) {
                    int c2 = cc - DIM;
                    *(uint32_t*)&g_kh[(size_t)r0 * KVDIM + c2] = f2h2(v0, v1);
                    *(uint32_t*)&g_kh[(size_t)r1 * KVDIM + c2] = f2h2(v2, v3);
                } else {
                    int c2 = cc - DIM - KVDIM;
                    *(uint32_t*)&g_vh[(size_t)r0 * KVDIM + c2] = f2h2(v0, v1);
                    *(uint32_t*)&g_vh[(size_t)r1 * KVDIM + c2] = f2h2(v2, v3);
                }
            } else {
                if (sizeof(OutT) == 4) {
                    float2 t0; t0.x = v0; t0.y = v1;
                    float2 t1; t1.x = v2; t1.y = v3;
                    *(float2*)&((float*)C)[(size_t)r0 * N + cc] = t0;
                    *(float2*)&((float*)C)[(size_t)r1 * N + cc] = t1;
                } else {
                    *(uint32_t*)&((__half*)C)[(size_t)r0 * N + cc] = f2h2(v0, v1);
                    *(uint32_t*)&((__half*)C)[(size_t)r1 * N + cc] = f2h2(v2, v3);
                }
            }
        }
    }
}

// ---------------- fused prep: x conv + all 4 weight transposes, ONE launch --
// Block ranges (256 threads each):
//   [0, 8192)            x fp32 -> fp16   (SEQ*DIM/4 = 2,097,152 float4 / 256)
//   [8192, 16384)        wq^T  -> g_wh[0]           (128 x 64 tile blocks)
//   [16384, 18432)       wk^T  -> g_wh[DIM*DIM]     (32 x 64)
//   [18432, 20480)       wv^T  -> g_wh[(DIM+KVDIM)*DIM]
//   [20480, 28672)       wo^T  -> g_woh             (128 x 64)
#define PREP_BLOCKS 28672

__device__ __forceinline__ void tblock(const float* __restrict__ W,
                                       __half* __restrict__ WT,
                                       int K, int N, int bx, int by, int tid)
{
    __shared__ float t[64][33];
    const int tx = tid & 31, ty = tid >> 5;
    int x  = bx * 32 + tx;
    int y0 = by * 64;
    #pragma unroll
    for (int j = ty; j < 64; j += 8)
        t[j][tx] = W[(size_t)(y0 + j) * N + x];
    __syncthreads();
    int n0 = bx * 32;
    int kk = tx * 2;
    #pragma unroll
    for (int j = ty; j < 32; j += 8)
        *(uint32_t*)&WT[(size_t)(n0 + j) * K + y0 + kk] = f2h2(t[kk][j], t[kk + 1][j]);
}

__global__ __launch_bounds__(256)
void prep_all(const float* __restrict__ x,
              const float* __restrict__ wq, const float* __restrict__ wk,
              const float* __restrict__ wv, const float* __restrict__ wo)
{
    const int b = blockIdx.x, tid = threadIdx.x;
    if (b < 8192) {
        int i = b * 256 + tid;
        float4 v = ((const float4*)x)[i];
        uint2 o;
        o.x = f2h2(v.x, v.y);
        o.y = f2h2(v.z, v.w);
        ((uint2*)g_xh)[i] = o;
    } else if (b < 16384) {
        int r = b - 8192;                     // wq: N=4096 -> 128 x-blocks
        tblock(wq, g_wh, DIM, DIM, r & 127, r >> 7, tid);
    } else if (b < 18432) {
        int r = b - 16384;                    // wk: N=1024 -> 32 x-blocks
        tblock(wk, g_wh + (size_t)DIM * DIM, DIM, KVDIM, r & 31, r >> 5, tid);
    } else if (b < 20480) {
        int r = b - 18432;
        tblock(wv, g_wh + (size_t)(DIM + KVDIM) * DIM, DIM, KVDIM, r & 31, r >> 5, tid);
    } else {
        int r = b - 20480;
        tblock(wo, g_woh, DIM, DIM, r & 127, r >> 7, tid);
    }
}

// ---------------- causal flash attention (fp16 mma, GQA) --------------------
#define FKR   136                         // halves per K/V smem row
#define FTILE (64 * FKR * 2)              // 17408 B
#define F_SMEM (4 * FTILE)                // K0,V0,K1,V1

__device__ __forceinline__ void f_fill(uint32_t sbase, int buf, int kt,
                                       const __half* __restrict__ kb,
                                       const __half* __restrict__ vb, int tid)
{
    const uint32_t kd = sbase + buf * (2 * FTILE);
    const uint32_t vd = kd + FTILE;
    const __half* kg = kb + (size_t)(kt * 64) * KVDIM;
    const __half* vg = vb + (size_t)(kt * 64) * KVDIM;
    #pragma unroll
    for (int j = 0; j < 8; j++) {
        int idx = tid + j * 128;
        int r = idx >> 4, c = idx & 15;
        cpasync16(kd + r * 272 + c * 16, kg + (size_t)r * KVDIM + c * 8);
        cpasync16(vd + r * 272 + c * 16, vg + (size_t)r * KVDIM + c * 8);
    }
    CP_COMMIT();
}

__global__ __launch_bounds__(128, 3)
void flash_h(const __half* __restrict__ q, const __half* __restrict__ k,
             const __half* __restrict__ v, __half* __restrict__ o)
{
    extern __shared__ char smem[];
    const uint32_t sbase = smem_u32(smem);
    const int tid = threadIdx.x, lane = tid & 31, w = tid >> 5;
    const int g = lane >> 2, tg = lane & 3;
    const int h = blockIdx.y;
    const int qt = gridDim.x - 1 - blockIdx.x;   // longest CTAs launch first
    const int q0 = qt * 64, khd = h >> 2;

    const __half* kb = k + khd * HD;
    const __half* vb = v + khd * HD;

    // ---- stage Q tile into buf1-K region (unused at kt=0) + overlap fill0
    {
        const __half* qg = q + (size_t)q0 * DIM + h * HD;
        const uint32_t qdst = sbase + 2 * FTILE;   // buf1 K region
        #pragma unroll
        for (int j = 0; j < 8; j++) {
            int idx = tid + j * 128;
            int r = idx >> 4, c = idx & 15;
            cpasync16(qdst + r * 272 + c * 16, qg + (size_t)r * DIM + c * 8);
        }
        CP_COMMIT();
    }
    f_fill(sbase, 0, 0, kb, vb, tid);   // overlap K/V tile 0 with Q load
    CP_WAIT(1);                          // Q group done (fill0 may be pending)
    __syncthreads();

    uint32_t qa[8][4];
    {
        const uint32_t qoff = sbase + 2 * FTILE
            + (uint32_t)((w * 16 + (lane & 15)) * 272 + (lane >> 4) * 16);
        #pragma unroll
        for (int ks = 0; ks < 8; ks++) ldsm4(qa[ks], qoff + ks * 32);
    }
    __syncthreads();   // Q frags read before buf1 can be refilled

    float m0 = -1e30f, m1 = -1e30f, l0 = 0.f, l1 = 0.f;
    float oacc[16][4];
    #pragma unroll
    for (int nf = 0; nf < 16; nf++)
        #pragma unroll
        for (int c = 0; c < 4; c++) oacc[nf][c] = 0.f;

    const uint32_t kboff = (uint32_t)(((lane & 7) + ((lane >> 4) << 3)) * 272
                                      + ((lane >> 3) & 1) * 16);
    const uint32_t vboff = (uint32_t)(((lane & 7) + ((lane >> 3) & 1) * 8) * 272
                                      + (lane >> 4) * 16);

    for (int kt = 0; kt <= qt; kt++) {
        if (kt < qt) {
            f_fill(sbase, (kt + 1) & 1, kt + 1, kb, vb, tid);
            CP_WAIT(1);
        } else {
            CP_WAIT(0);
        }
        __syncthreads();
        const uint32_t kbase = sbase + (kt & 1) * (2 * FTILE);
        const uint32_t vbase = kbase + FTILE;

        // ---- S = Q @ K^T
        float s[8][4];
        #pragma unroll
        for (int nf = 0; nf < 8; nf++)
            #pragma unroll
            for (int c = 0; c < 4; c++) s[nf][c] = 0.f;
        #pragma unroll
        for (int ks = 0; ks < 8; ks++) {
            #pragma unroll
            for (int nbp = 0; nbp < 4; nbp++) {
                uint32_t b[4];
                ldsm4(b, kbase + kboff + nbp * 16 * 272 + ks * 32);
                mma16(s[nbp * 2],     qa[ks], b[0], b[1]);
                mma16(s[nbp * 2 + 1], qa[ks], b[2], b[3]);
            }
        }

        // ---- causal mask on diagonal tile
        if (kt == qt) {
            int r0 = w * 16 + g, r1 = r0 + 8;
            #pragma unroll
            for (int nf = 0; nf < 8; nf++) {
                int c = nf * 8 + tg * 2;
                if (c     > r0) s[nf][0] = -1e30f;
                if (c + 1 > r0) s[nf][1] = -1e30f;
                if (c     > r1) s[nf][2] = -1e30f;
                if (c + 1 > r1) s[nf][3] = -1e30f;
            }
        }

        // ---- online softmax; P packed to fp16 registers
        float mx0 = -1e30f, mx1 = -1e30f;
        #pragma unroll
        for (int nf = 0; nf < 8; nf++) {
            mx0 = fmaxf(mx0, fmaxf(s[nf][0], s[nf][1]));
            mx1 = fmaxf(mx1, fmaxf(s[nf][2], s[nf][3]));
        }
        mx0 = fmaxf(mx0, __shfl_xor_sync(0xffffffffu, mx0, 1));
        mx0 = fmaxf(mx0, __shfl_xor_sync(0xffffffffu, mx0, 2));
        mx1 = fmaxf(mx1, __shfl_xor_sync(0xffffffffu, mx1, 1));
        mx1 = fmaxf(mx1, __shfl_xor_sync(0xffffffffu, mx1, 2));

        float mn0 = fmaxf(m0, mx0), mn1 = fmaxf(m1, mx1);
        float al0 = __expf(m0 - mn0), al1 = __expf(m1 - mn1);
        float rs0 = 0.f, rs1 = 0.f;
        uint32_t ph[8][2];
        #pragma unroll
        for (int nf = 0; nf < 8; nf++) {
            float p0 = __expf(s[nf][0] - mn0);
            float p1 = __expf(s[nf][1] - mn0);
            float p2 = __expf(s[nf][2] - mn1);
            float p3 = __expf(s[nf][3] - mn1);
            rs0 += p0 + p1; rs1 += p2 + p3;
            ph[nf][0] = f2h2(p0, p1);   // row g
            ph[nf][1] = f2h2(p2, p3);   // row g+8
        }
        rs0 += __shfl_xor_sync(0xffffffffu, rs0, 1);
        rs0 += __shfl_xor_sync(0xffffffffu, rs0, 2);
        rs1 += __shfl_xor_sync(0xffffffffu, rs1, 1);
        rs1 += __shfl_xor_sync(0xffffffffu, rs1, 2);
        l0 = l0 * al0 + rs0;  l1 = l1 * al1 + rs1;
        m0 = mn0;  m1 = mn1;
        #pragma unroll
        for (int nf = 0; nf < 16; nf++) {
            oacc[nf][0] *= al0; oacc[nf][1] *= al0;
            oacc[nf][2] *= al1; oacc[nf][3] *= al1;
        }

        // ---- O += P @ V   (V via ldmatrix.trans)
        #pragma unroll
        for (int ksv = 0; ksv < 4; ksv++) {
            uint32_t a[4];
            a[0] = ph[2 * ksv][0];     a[1] = ph[2 * ksv][1];
            a[2] = ph[2 * ksv + 1][0]; a[3] = ph[2 * ksv + 1][1];
            #pragma unroll
            for (int nbp = 0; nbp < 8; nbp++) {
                uint32_t b[4];
                ldsm4t(b, vbase + vboff + ksv * 16 * 272 + nbp * 32);
                mma16(oacc[nbp * 2],     a, b[0], b[1]);
                mma16(oacc[nbp * 2 + 1], a, b[2], b[3]);
            }
        }
        __syncthreads();   // all warps done with this buffer before refill
    }

    // ---- epilogue: fp16 store (A operand of the wo GEMM)
    float inv0 = 1.f / l0, inv1 = 1.f / l1;
    __half* o0 = o + (size_t)(q0 + w * 16 + g) * DIM + h * HD;
    __half* o1 = o0 + (size_t)8 * DIM;
    #pragma unroll
    for (int nf = 0; nf < 16; nf++) {
        *(uint32_t*)&o0[nf * 8 + tg * 2] = f2h2(oacc[nf][0] * inv0, oacc[nf][1] * inv0);
        *(uint32_t*)&o1[nf * 8 + tg * 2] = f2h2(oacc[nf][2] * inv1, oacc[nf][3] * inv1);
    }
}

// ---------------- launch ------------------------------------------------------
extern "C" void kernel_launch(void* const* d_in, const int* in_sizes, int n_in,
                              void* d_out, int out_size)
{
    const float* x  = (const float*)d_in[0];
    // d_in[1] = cache_kv: unused (start_pos==0 => cache is pass-through)
    const float* fr = (const float*)d_in[2];
    const float* wq = (const float*)d_in[3];
    const float* wk = (const float*)d_in[4];
    const float* wv = (const float*)d_in[5];
    const float* wo = (const float*)d_in[6];
    float* out = (float*)d_out;

    __half *pxh, *pqh, *pkh, *pvh, *pah, *pwh, *pwoh;
    cudaGetSymbolAddress((void**)&pxh,  g_xh);
    cudaGetSymbolAddress((void**)&pqh,  g_qh);
    cudaGetSymbolAddress((void**)&pkh,  g_kh);
    cudaGetSymbolAddress((void**)&pvh,  g_vh);
    cudaGetSymbolAddress((void**)&pah,  g_ah);
    cudaGetSymbolAddress((void**)&pwh,  g_wh);
    cudaGetSymbolAddress((void**)&pwoh, g_woh);

    cudaFuncSetAttribute((gemm_h<__half, 3>),
                         cudaFuncAttributeMaxDynamicSharedMemorySize, G_SMEM);
    cudaFuncSetAttribute((gemm_h<float, 0>),
                         cudaFuncAttributeMaxDynamicSharedMemorySize, G_SMEM);
    cudaFuncSetAttribute(flash_h,
                         cudaFuncAttributeMaxDynamicSharedMemorySize, F_SMEM);

    // --- fused prep: x conversion + all weight transposes, one launch ---
    prep_all<<<PREP_BLOCKS, 256>>>(x, wq, wk, wv, wo);

    // --- fused QKV projection (one launch; rope/scale/routing in epilogue) ---
    gemm_h<__half, 3><<<dim3(NQKV / 128, SEQ / 128), 256, G_SMEM>>>(
        pxh, pwh, pqh /*unused*/, fr, NQKV, DIM);

    // --- causal GQA flash attention (fp16 mma) ---
    flash_h<<<dim3(SEQ / 64, NH), 128, F_SMEM>>>(pqh, pkh, pvh, pah);

    // --- output projection ---
    gemm_h<float, 0><<<dim3(DIM / 128, SEQ / 128), 256, G_SMEM>>>(
        pah, pwoh, out, fr, DIM, DIM);
}